// round 3
// baseline (speedup 1.0000x reference)
#include <cuda_runtime.h>
#include <cuda_bf16.h>
#include <math.h>

// Problem-size constants (dataset fixed).
#define MAXN 100000
#define MAXE 1600000

// ---------------- scratch (no allocations allowed -> __device__ globals) ----
__device__ __align__(16) int   g_edeg[MAXN];       // in-degree (edges only)
__device__ __align__(16) float g_dis[MAXN];        // rsqrt(deg+1)
__device__ __align__(16) int   g_off[MAXN + 1];    // CSR offsets by dst
__device__ __align__(16) int   g_cur[MAXN];        // fill cursors
__device__ __align__(16) int   g_col[MAXE];        // CSR column = src node
__device__ __align__(16) float g_bufA[(size_t)MAXN * 128];  // pre-aggregation h
__device__ __align__(16) float g_bufB[(size_t)MAXN * 128];  // post-layer output
__device__ __align__(16) float g_pooled[64];

// ---------------- zero scratch ---------------------------------------------
__global__ void zero_scratch_kernel(int n) {
    int i = blockIdx.x * blockDim.x + threadIdx.x;
    int stride = gridDim.x * blockDim.x;
    for (int k = i; k < n; k += stride) {
        g_edeg[k] = 0;
        g_cur[k]  = 0;
    }
    if (i < 64) g_pooled[i] = 0.0f;
}

// ---------------- degree histogram over dst (edge_index is int32!) ---------
__global__ void degree_kernel(const int* __restrict__ dst, int e) {
    int i = blockIdx.x * blockDim.x + threadIdx.x;
    int stride = gridDim.x * blockDim.x;
    for (int k = i; k < e; k += stride)
        atomicAdd(&g_edeg[dst[k]], 1);
}

__global__ void dis_kernel(int n) {
    int i = blockIdx.x * blockDim.x + threadIdx.x;
    if (i < n) g_dis[i] = rsqrtf((float)(g_edeg[i] + 1));  // +1 self loop
}

// ---------------- exclusive scan of g_edeg -> g_off (one block) ------------
__global__ void scan_kernel(int n) {
    __shared__ int ssum[1024];
    int t = threadIdx.x;
    int chunk = (n + 1023) >> 10;
    int beg = min(t * chunk, n);
    int end = min(beg + chunk, n);
    int s = 0;
    for (int i = beg; i < end; i++) s += g_edeg[i];
    ssum[t] = s;
    __syncthreads();
    for (int off = 1; off < 1024; off <<= 1) {
        int v = 0;
        if (t >= off) v = ssum[t - off];
        __syncthreads();
        ssum[t] += v;
        __syncthreads();
    }
    int run = (t == 0) ? 0 : ssum[t - 1];
    for (int i = beg; i < end; i++) {
        g_off[i] = run;
        run += g_edeg[i];
    }
    if (t == 1023) g_off[n] = ssum[1023];
}

// ---------------- CSR fill --------------------------------------------------
__global__ void fill_kernel(const int* __restrict__ src,
                            const int* __restrict__ dst, int e) {
    int i = blockIdx.x * blockDim.x + threadIdx.x;
    int stride = gridDim.x * blockDim.x;
    for (int k = i; k < e; k += stride) {
        int d = dst[k];
        int p = atomicAdd(&g_cur[d], 1);
        g_col[g_off[d] + p] = src[k];
    }
}

// ---------------- SGEMM: C[n,HOUT] = A[n,K] * W[K,HOUT] --------------------
// block 256 threads; tile 64 rows x HOUT cols; each thread 4 rows x (HOUT/16) cols
template <int K, int HOUT>
__global__ void gemm_kernel(const float* __restrict__ A,
                            const float* __restrict__ W,
                            float* __restrict__ C, int n) {
    constexpr int KC = 32;
    constexpr int CW = HOUT / 16;
    __shared__ float sA[64][KC + 1];
    __shared__ float sB[KC][HOUT];

    int tid = threadIdx.x;
    int tx = tid & 15;       // col group
    int ty = tid >> 4;       // row group
    int rowBase = blockIdx.x * 64;

    float acc[4][CW];
#pragma unroll
    for (int r = 0; r < 4; r++)
#pragma unroll
        for (int c = 0; c < CW; c++) acc[r][c] = 0.0f;

    for (int kc = 0; kc < K; kc += KC) {
        for (int i = tid; i < 64 * KC; i += 256) {
            int r = i / KC, k = i % KC;
            int row = rowBase + r;
            sA[r][k] = (row < n) ? A[(size_t)row * K + kc + k] : 0.0f;
        }
        for (int i = tid; i < KC * HOUT; i += 256) {
            int k = i / HOUT, j = i % HOUT;
            sB[k][j] = W[(size_t)(kc + k) * HOUT + j];
        }
        __syncthreads();
#pragma unroll
        for (int kk = 0; kk < KC; kk++) {
            float a[4], b[CW];
#pragma unroll
            for (int r = 0; r < 4; r++) a[r] = sA[ty * 4 + r][kk];
#pragma unroll
            for (int c = 0; c < CW; c++) b[c] = sB[kk][tx * CW + c];
#pragma unroll
            for (int r = 0; r < 4; r++)
#pragma unroll
                for (int c = 0; c < CW; c++) acc[r][c] = fmaf(a[r], b[c], acc[r][c]);
        }
        __syncthreads();
    }
#pragma unroll
    for (int r = 0; r < 4; r++) {
        int row = rowBase + ty * 4 + r;
        if (row < n) {
#pragma unroll
            for (int c = 0; c < CW; c++)
                C[(size_t)row * HOUT + tx * CW + c] = acc[r][c];
        }
    }
}

// ---------------- aggregation (gather, atomic-free) ------------------------
// out[d] = relu( dis[d] * sum_{s in N(d)} dis[s]*h[s]  +  dis[d]^2 * h[d] + b )
// one warp per node
template <int HOUT>
__global__ void agg_kernel(const float* __restrict__ h,
                           const float* __restrict__ bias,
                           float* __restrict__ out, int n) {
    int w = (blockIdx.x * blockDim.x + threadIdx.x) >> 5;
    int lane = threadIdx.x & 31;
    if (w >= n) return;

    int beg = g_off[w], end = g_off[w + 1];
    float dd = g_dis[w];

    if constexpr (HOUT == 128) {
        float4 acc = make_float4(0.f, 0.f, 0.f, 0.f);
        for (int i = beg; i < end; i++) {
            int s = g_col[i];
            float wt = g_dis[s];
            float4 v = reinterpret_cast<const float4*>(h + (size_t)s * 128)[lane];
            acc.x = fmaf(wt, v.x, acc.x);
            acc.y = fmaf(wt, v.y, acc.y);
            acc.z = fmaf(wt, v.z, acc.z);
            acc.w = fmaf(wt, v.w, acc.w);
        }
        float4 sv = reinterpret_cast<const float4*>(h + (size_t)w * 128)[lane];
        float4 bb = reinterpret_cast<const float4*>(bias)[lane];
        float d2 = dd * dd;
        float4 o;
        o.x = fmaxf(fmaf(dd, acc.x, fmaf(d2, sv.x, bb.x)), 0.f);
        o.y = fmaxf(fmaf(dd, acc.y, fmaf(d2, sv.y, bb.y)), 0.f);
        o.z = fmaxf(fmaf(dd, acc.z, fmaf(d2, sv.z, bb.z)), 0.f);
        o.w = fmaxf(fmaf(dd, acc.w, fmaf(d2, sv.w, bb.w)), 0.f);
        reinterpret_cast<float4*>(out + (size_t)w * 128)[lane] = o;
    } else {  // HOUT == 64
        float2 acc = make_float2(0.f, 0.f);
        for (int i = beg; i < end; i++) {
            int s = g_col[i];
            float wt = g_dis[s];
            float2 v = reinterpret_cast<const float2*>(h + (size_t)s * 64)[lane];
            acc.x = fmaf(wt, v.x, acc.x);
            acc.y = fmaf(wt, v.y, acc.y);
        }
        float2 sv = reinterpret_cast<const float2*>(h + (size_t)w * 64)[lane];
        float2 bb = reinterpret_cast<const float2*>(bias)[lane];
        float d2 = dd * dd;
        float2 o;
        o.x = fmaxf(fmaf(dd, acc.x, fmaf(d2, sv.x, bb.x)), 0.f);
        o.y = fmaxf(fmaf(dd, acc.y, fmaf(d2, sv.y, bb.y)), 0.f);
        reinterpret_cast<float2*>(out + (size_t)w * 64)[lane] = o;
    }
}

// ---------------- mean pool over nodes (h stride 64) -----------------------
__global__ void pool_kernel(const float* __restrict__ h, int n) {
    int f = threadIdx.x & 63;
    int rg = threadIdx.x >> 6;  // 0..3
    float acc = 0.f;
    for (int r = blockIdx.x * 4 + rg; r < n; r += gridDim.x * 4)
        acc += h[(size_t)r * 64 + f];
    __shared__ float sp[256];
    sp[threadIdx.x] = acc;
    __syncthreads();
    if (threadIdx.x < 64) {
        float v = sp[threadIdx.x] + sp[threadIdx.x + 64] +
                  sp[threadIdx.x + 128] + sp[threadIdx.x + 192];
        atomicAdd(&g_pooled[f], v);
    }
}

// ---------------- classifier + softmax -------------------------------------
__global__ void cls_kernel(const float* __restrict__ Wc1, const float* __restrict__ bc1,
                           const float* __restrict__ Wc2, const float* __restrict__ bc2,
                           float* __restrict__ out, float invN) {
    __shared__ float z[32];
    int t = threadIdx.x;
    if (t < 32) {
        float a = bc1[t];
        for (int i = 0; i < 64; i++)
            a = fmaf(g_pooled[i] * invN, Wc1[i * 32 + t], a);
        z[t] = fmaxf(a, 0.f);
    }
    __syncthreads();
    if (t == 0) {
        float l0 = bc2[0], l1 = bc2[1];
        for (int j = 0; j < 32; j++) {
            l0 = fmaf(z[j], Wc2[j * 2 + 0], l0);
            l1 = fmaf(z[j], Wc2[j * 2 + 1], l1);
        }
        float m = fmaxf(l0, l1);
        float e0 = expf(l0 - m), e1 = expf(l1 - m);
        float s = e0 + e1;
        out[0] = e0 / s;
        out[1] = e1 / s;
    }
}

// ---------------- launch ----------------------------------------------------
extern "C" void kernel_launch(void* const* d_in, const int* in_sizes, int n_in,
                              void* d_out, int out_size) {
    const float* x   = (const float*)d_in[0];
    const int*   ei  = (const int*)d_in[1];   // int32! (JAX x64 disabled)
    const float* W1  = (const float*)d_in[2];
    const float* b1  = (const float*)d_in[3];
    const float* W2  = (const float*)d_in[4];
    const float* b2  = (const float*)d_in[5];
    const float* W3  = (const float*)d_in[6];
    const float* b3  = (const float*)d_in[7];
    const float* Wc1 = (const float*)d_in[8];
    const float* bc1 = (const float*)d_in[9];
    const float* Wc2 = (const float*)d_in[10];
    const float* bc2 = (const float*)d_in[11];
    float* out = (float*)d_out;

    int n = in_sizes[0] / 64;
    int e = in_sizes[1] / 2;
    const int* src = ei;
    const int* dst = ei + e;

    float* bufA;  cudaGetSymbolAddress((void**)&bufA, g_bufA);
    float* bufB;  cudaGetSymbolAddress((void**)&bufB, g_bufB);

    zero_scratch_kernel<<<512, 256>>>(n);
    degree_kernel<<<2048, 256>>>(dst, e);
    dis_kernel<<<(n + 255) / 256, 256>>>(n);
    scan_kernel<<<1, 1024>>>(n);
    fill_kernel<<<2048, 256>>>(src, dst, e);

    // layer 1: (N,64)@(64,128) -> agg -> relu
    gemm_kernel<64, 128><<<(n + 63) / 64, 256>>>(x, W1, bufA, n);
    agg_kernel<128><<<(n + 7) / 8, 256>>>(bufA, b1, bufB, n);
    // layer 2: (N,128)@(128,128)
    gemm_kernel<128, 128><<<(n + 63) / 64, 256>>>(bufB, W2, bufA, n);
    agg_kernel<128><<<(n + 7) / 8, 256>>>(bufA, b2, bufB, n);
    // layer 3: (N,128)@(128,64)
    gemm_kernel<128, 64><<<(n + 63) / 64, 256>>>(bufB, W3, bufA, n);
    agg_kernel<64><<<(n + 7) / 8, 256>>>(bufA, b3, bufB, n);

    pool_kernel<<<256, 256>>>(bufB, n);
    cls_kernel<<<1, 64>>>(Wc1, bc1, Wc2, bc2, out, 1.0f / (float)n);
}

// round 4
// speedup vs baseline: 2.0237x; 2.0237x over previous
#include <cuda_runtime.h>
#include <cuda_bf16.h>
#include <math.h>

#define MAXN 100000
#define MAXE 1600000
#define SCAN_CHUNK 1024   // elements per block in scan (256 thr x 4)
#define MAXNB ((MAXN + SCAN_CHUNK - 1) / SCAN_CHUNK)   // 98

// ---------------- scratch ---------------------------------------------------
__device__ __align__(16) int   g_edeg[MAXN];
__device__ __align__(16) float g_dis[MAXN];
__device__ __align__(16) int   g_off[MAXN + 1];
__device__ __align__(16) int   g_cur[MAXN];
__device__ __align__(16) int   g_col[MAXE];
__device__ __align__(16) int   g_bsum[128];
__device__ __align__(16) int   g_boff[128];
__device__ __align__(16) __nv_bfloat16 g_hA[(size_t)MAXN * 128];
__device__ __align__(16) __nv_bfloat16 g_hB[(size_t)MAXN * 128];
__device__ __align__(16) float g_pooled[64];

// ---------------- zero scratch ----------------------------------------------
__global__ void zero_scratch_kernel(int n) {
    int i = blockIdx.x * blockDim.x + threadIdx.x;
    int stride = gridDim.x * blockDim.x;
    for (int k = i; k < n; k += stride) {
        g_edeg[k] = 0;
        g_cur[k]  = 0;
    }
    if (i < 64) g_pooled[i] = 0.0f;
}

// ---------------- degree histogram over dst ---------------------------------
__global__ void degree_kernel(const int* __restrict__ dst, int e) {
    int i = blockIdx.x * blockDim.x + threadIdx.x;
    int stride = gridDim.x * blockDim.x;
    for (int k = i; k < e; k += stride)
        atomicAdd(&g_edeg[dst[k]], 1);
}

// ---------------- scan phase A: per-block sums + dis ------------------------
__global__ void scanA_kernel(int n) {
    __shared__ int ssum[8];
    int base = blockIdx.x * SCAN_CHUNK + threadIdx.x * 4;
    int s = 0;
#pragma unroll
    for (int j = 0; j < 4; j++) {
        int idx = base + j;
        if (idx < n) {
            int d = g_edeg[idx];
            s += d;
            g_dis[idx] = rsqrtf((float)(d + 1));
        }
    }
#pragma unroll
    for (int o = 16; o > 0; o >>= 1) s += __shfl_down_sync(0xffffffffu, s, o);
    if ((threadIdx.x & 31) == 0) ssum[threadIdx.x >> 5] = s;
    __syncthreads();
    if (threadIdx.x == 0) {
        int t = 0;
#pragma unroll
        for (int w = 0; w < 8; w++) t += ssum[w];
        g_bsum[blockIdx.x] = t;
    }
}

// ---------------- scan phase B: scan of block sums (nb <= 128) --------------
__global__ void scanB_kernel(int nb, int n) {
    __shared__ int sh[128];
    int t = threadIdx.x;
    int v = (t < nb) ? g_bsum[t] : 0;
    sh[t] = v;
    __syncthreads();
#pragma unroll
    for (int o = 1; o < 128; o <<= 1) {
        int u = (t >= o) ? sh[t - o] : 0;
        __syncthreads();
        sh[t] += u;
        __syncthreads();
    }
    if (t < nb) g_boff[t] = sh[t] - v;       // exclusive
    if (t == nb - 1) g_off[n] = sh[t];       // total
}

// ---------------- scan phase C: local scan + add block offset ---------------
__global__ void scanC_kernel(int n) {
    __shared__ int sh[256];
    int t = threadIdx.x;
    int base = blockIdx.x * SCAN_CHUNK + t * 4;
    int d[4];
    int s = 0;
#pragma unroll
    for (int j = 0; j < 4; j++) {
        int idx = base + j;
        d[j] = (idx < n) ? g_edeg[idx] : 0;
        s += d[j];
    }
    sh[t] = s;
    __syncthreads();
#pragma unroll
    for (int o = 1; o < 256; o <<= 1) {
        int u = (t >= o) ? sh[t - o] : 0;
        __syncthreads();
        sh[t] += u;
        __syncthreads();
    }
    int run = g_boff[blockIdx.x] + sh[t] - s;   // exclusive prefix for this thread
#pragma unroll
    for (int j = 0; j < 4; j++) {
        int idx = base + j;
        if (idx < n) g_off[idx] = run;
        run += d[j];
    }
}

// ---------------- CSR fill --------------------------------------------------
__global__ void fill_kernel(const int* __restrict__ src,
                            const int* __restrict__ dst, int e) {
    int i = blockIdx.x * blockDim.x + threadIdx.x;
    int stride = gridDim.x * blockDim.x;
    for (int k = i; k < e; k += stride) {
        int d = dst[k];
        int p = atomicAdd(&g_cur[d], 1);
        g_col[g_off[d] + p] = src[k];
    }
}

// ---------------- x -> bf16 -------------------------------------------------
__global__ void cvt_kernel(const float* __restrict__ x, __nv_bfloat16* __restrict__ o,
                           int total) {
    int i = blockIdx.x * blockDim.x + threadIdx.x;
    int stride = gridDim.x * blockDim.x;
    for (int k = i; k < total; k += stride)
        o[k] = __float2bfloat16_rn(x[k]);
}

// ---------------- GEMM: C[n,HOUT] = A[n,K](bf16) * W[K,HOUT](f32) -----------
// optional fused bias+relu; output bf16. 256 thr, tile 64 x HOUT.
template <int K, int HOUT, bool BIASRELU>
__global__ void gemm_kernel(const __nv_bfloat16* __restrict__ A,
                            const float* __restrict__ W,
                            const float* __restrict__ bias,
                            __nv_bfloat16* __restrict__ C, int n) {
    constexpr int KC = 32;
    constexpr int CW = HOUT / 16;
    __shared__ float sA[64][KC + 1];
    __shared__ float sB[KC][HOUT];

    int tid = threadIdx.x;
    int tx = tid & 15;
    int ty = tid >> 4;
    int rowBase = blockIdx.x * 64;

    float acc[4][CW];
#pragma unroll
    for (int r = 0; r < 4; r++)
#pragma unroll
        for (int c = 0; c < CW; c++) acc[r][c] = 0.0f;

    for (int kc = 0; kc < K; kc += KC) {
        for (int i = tid; i < 64 * KC; i += 256) {
            int r = i / KC, k = i % KC;
            int row = rowBase + r;
            sA[r][k] = (row < n) ? __bfloat162float(A[(size_t)row * K + kc + k]) : 0.0f;
        }
        for (int i = tid; i < KC * HOUT; i += 256) {
            int k = i / HOUT, j = i % HOUT;
            sB[k][j] = W[(size_t)(kc + k) * HOUT + j];
        }
        __syncthreads();
#pragma unroll
        for (int kk = 0; kk < KC; kk++) {
            float a[4], b[CW];
#pragma unroll
            for (int r = 0; r < 4; r++) a[r] = sA[ty * 4 + r][kk];
#pragma unroll
            for (int c = 0; c < CW; c++) b[c] = sB[kk][tx * CW + c];
#pragma unroll
            for (int r = 0; r < 4; r++)
#pragma unroll
                for (int c = 0; c < CW; c++) acc[r][c] = fmaf(a[r], b[c], acc[r][c]);
        }
        __syncthreads();
    }
#pragma unroll
    for (int r = 0; r < 4; r++) {
        int row = rowBase + ty * 4 + r;
        if (row < n) {
#pragma unroll
            for (int c = 0; c < CW; c++) {
                float v = acc[r][c];
                if (BIASRELU) v = fmaxf(v + bias[tx * CW + c], 0.0f);
                C[(size_t)row * HOUT + tx * CW + c] = __float2bfloat16_rn(v);
            }
        }
    }
}

// ---------------- aggregation (gather, atomic-free, bf16 tables) ------------
// out[d] = [relu]( dis[d]*sum_{s} dis[s]*h[s] + dis[d]^2*h[d] [+ b] )
// one warp per node.
template <int W, bool BIASRELU>
__global__ void agg_kernel(const __nv_bfloat16* __restrict__ h,
                           const float* __restrict__ bias,
                           __nv_bfloat16* __restrict__ out, int n) {
    int w = (blockIdx.x * blockDim.x + threadIdx.x) >> 5;
    int lane = threadIdx.x & 31;
    if (w >= n) return;

    int beg = g_off[w], end = g_off[w + 1];
    float dd = g_dis[w];
    float d2 = dd * dd;

    if constexpr (W == 128) {
        // lane covers 4 features via one uint2 (4 bf16)
        float4 acc = make_float4(0.f, 0.f, 0.f, 0.f);
        for (int i = beg; i < end; i++) {
            int s = g_col[i];
            float wt = g_dis[s];
            uint2 u = reinterpret_cast<const uint2*>(h + (size_t)s * 128)[lane];
            __nv_bfloat162 p0 = *reinterpret_cast<__nv_bfloat162*>(&u.x);
            __nv_bfloat162 p1 = *reinterpret_cast<__nv_bfloat162*>(&u.y);
            acc.x = fmaf(wt, __bfloat162float(p0.x), acc.x);
            acc.y = fmaf(wt, __bfloat162float(p0.y), acc.y);
            acc.z = fmaf(wt, __bfloat162float(p1.x), acc.z);
            acc.w = fmaf(wt, __bfloat162float(p1.y), acc.w);
        }
        uint2 us = reinterpret_cast<const uint2*>(h + (size_t)w * 128)[lane];
        __nv_bfloat162 s0 = *reinterpret_cast<__nv_bfloat162*>(&us.x);
        __nv_bfloat162 s1 = *reinterpret_cast<__nv_bfloat162*>(&us.y);
        float4 o;
        o.x = fmaf(dd, acc.x, d2 * __bfloat162float(s0.x));
        o.y = fmaf(dd, acc.y, d2 * __bfloat162float(s0.y));
        o.z = fmaf(dd, acc.z, d2 * __bfloat162float(s1.x));
        o.w = fmaf(dd, acc.w, d2 * __bfloat162float(s1.y));
        if (BIASRELU) {
            float4 bb = reinterpret_cast<const float4*>(bias)[lane];
            o.x = fmaxf(o.x + bb.x, 0.f);
            o.y = fmaxf(o.y + bb.y, 0.f);
            o.z = fmaxf(o.z + bb.z, 0.f);
            o.w = fmaxf(o.w + bb.w, 0.f);
        }
        uint2 r;
        __nv_bfloat162 r0 = __floats2bfloat162_rn(o.x, o.y);
        __nv_bfloat162 r1 = __floats2bfloat162_rn(o.z, o.w);
        r.x = *reinterpret_cast<unsigned*>(&r0);
        r.y = *reinterpret_cast<unsigned*>(&r1);
        reinterpret_cast<uint2*>(out + (size_t)w * 128)[lane] = r;
    } else {  // W == 64: lane covers 2 features via one uint32
        float2 acc = make_float2(0.f, 0.f);
        for (int i = beg; i < end; i++) {
            int s = g_col[i];
            float wt = g_dis[s];
            unsigned u = reinterpret_cast<const unsigned*>(h + (size_t)s * 64)[lane];
            __nv_bfloat162 p = *reinterpret_cast<__nv_bfloat162*>(&u);
            acc.x = fmaf(wt, __bfloat162float(p.x), acc.x);
            acc.y = fmaf(wt, __bfloat162float(p.y), acc.y);
        }
        unsigned us = reinterpret_cast<const unsigned*>(h + (size_t)w * 64)[lane];
        __nv_bfloat162 sp = *reinterpret_cast<__nv_bfloat162*>(&us);
        float2 o;
        o.x = fmaf(dd, acc.x, d2 * __bfloat162float(sp.x));
        o.y = fmaf(dd, acc.y, d2 * __bfloat162float(sp.y));
        if (BIASRELU) {
            float2 bb = reinterpret_cast<const float2*>(bias)[lane];
            o.x = fmaxf(o.x + bb.x, 0.f);
            o.y = fmaxf(o.y + bb.y, 0.f);
        }
        __nv_bfloat162 r0 = __floats2bfloat162_rn(o.x, o.y);
        reinterpret_cast<unsigned*>(out + (size_t)w * 64)[lane] =
            *reinterpret_cast<unsigned*>(&r0);
    }
}

// ---------------- mean pool (bf16 in, width 64) -----------------------------
__global__ void pool_kernel(const __nv_bfloat16* __restrict__ h, int n) {
    int f = threadIdx.x & 63;
    int rg = threadIdx.x >> 6;
    float acc = 0.f;
    for (int r = blockIdx.x * 4 + rg; r < n; r += gridDim.x * 4)
        acc += __bfloat162float(h[(size_t)r * 64 + f]);
    __shared__ float sp[256];
    sp[threadIdx.x] = acc;
    __syncthreads();
    if (threadIdx.x < 64) {
        float v = sp[threadIdx.x] + sp[threadIdx.x + 64] +
                  sp[threadIdx.x + 128] + sp[threadIdx.x + 192];
        atomicAdd(&g_pooled[f], v);
    }
}

// ---------------- classifier + softmax --------------------------------------
__global__ void cls_kernel(const float* __restrict__ Wc1, const float* __restrict__ bc1,
                           const float* __restrict__ Wc2, const float* __restrict__ bc2,
                           float* __restrict__ out, float invN) {
    __shared__ float z[32];
    int t = threadIdx.x;
    if (t < 32) {
        float a = bc1[t];
        for (int i = 0; i < 64; i++)
            a = fmaf(g_pooled[i] * invN, Wc1[i * 32 + t], a);
        z[t] = fmaxf(a, 0.f);
    }
    __syncthreads();
    if (t == 0) {
        float l0 = bc2[0], l1 = bc2[1];
        for (int j = 0; j < 32; j++) {
            l0 = fmaf(z[j], Wc2[j * 2 + 0], l0);
            l1 = fmaf(z[j], Wc2[j * 2 + 1], l1);
        }
        float m = fmaxf(l0, l1);
        float e0 = expf(l0 - m), e1 = expf(l1 - m);
        float s = e0 + e1;
        out[0] = e0 / s;
        out[1] = e1 / s;
    }
}

// ---------------- launch -----------------------------------------------------
extern "C" void kernel_launch(void* const* d_in, const int* in_sizes, int n_in,
                              void* d_out, int out_size) {
    const float* x   = (const float*)d_in[0];
    const int*   ei  = (const int*)d_in[1];   // int32 edge_index
    const float* W1  = (const float*)d_in[2];
    const float* b1  = (const float*)d_in[3];
    const float* W2  = (const float*)d_in[4];
    const float* b2  = (const float*)d_in[5];
    const float* W3  = (const float*)d_in[6];
    const float* b3  = (const float*)d_in[7];
    const float* Wc1 = (const float*)d_in[8];
    const float* bc1 = (const float*)d_in[9];
    const float* Wc2 = (const float*)d_in[10];
    const float* bc2 = (const float*)d_in[11];
    float* out = (float*)d_out;

    int n = in_sizes[0] / 64;
    int e = in_sizes[1] / 2;
    const int* src = ei;
    const int* dst = ei + e;
    int nb = (n + SCAN_CHUNK - 1) / SCAN_CHUNK;

    __nv_bfloat16* A;  cudaGetSymbolAddress((void**)&A, g_hA);
    __nv_bfloat16* B;  cudaGetSymbolAddress((void**)&B, g_hB);

    // graph prep
    zero_scratch_kernel<<<512, 256>>>(n);
    degree_kernel<<<2048, 256>>>(dst, e);
    scanA_kernel<<<nb, 256>>>(n);
    scanB_kernel<<<1, 128>>>(nb, n);
    scanC_kernel<<<nb, 256>>>(n);
    fill_kernel<<<2048, 256>>>(src, dst, e);

    // x -> bf16
    cvt_kernel<<<1024, 256>>>(x, A, n * 64);

    // layer 1 (reordered): aggregate x first (width 64), then GEMM + bias + relu
    agg_kernel<64, false><<<(n + 7) / 8, 256>>>(A, nullptr, B, n);
    gemm_kernel<64, 128, true><<<(n + 63) / 64, 256>>>(B, W1, b1, A, n);
    // layer 2: GEMM then agg(+b2,relu)
    gemm_kernel<128, 128, false><<<(n + 63) / 64, 256>>>(A, W2, nullptr, B, n);
    agg_kernel<128, true><<<(n + 7) / 8, 256>>>(B, b2, A, n);
    // layer 3: GEMM (128->64) then agg(+b3,relu)
    gemm_kernel<128, 64, false><<<(n + 63) / 64, 256>>>(A, W3, nullptr, B, n);
    agg_kernel<64, true><<<(n + 7) / 8, 256>>>(B, b3, A, n);

    // pool + classifier
    pool_kernel<<<256, 256>>>(A, n);
    cls_kernel<<<1, 64>>>(Wc1, bc1, Wc2, bc2, out, 1.0f / (float)n);
}

// round 5
// speedup vs baseline: 2.4913x; 1.2311x over previous
#include <cuda_runtime.h>
#include <cuda_bf16.h>
#include <math.h>

#define MAXN 100000
#define MAXE 1600000
#define SCAN_CHUNK 1024

// ---------------- scratch ---------------------------------------------------
__device__ __align__(16) int   g_edeg[MAXN];
__device__ __align__(16) float g_dis[MAXN];
__device__ __align__(16) int   g_off[MAXN + 1];
__device__ __align__(16) int   g_cur[MAXN];
__device__ __align__(16) int   g_col[MAXE];
__device__ __align__(16) int   g_bsum[128];
__device__ __align__(16) int   g_boff[128];
__device__ __align__(16) __nv_bfloat16 g_hA[(size_t)MAXN * 128];
__device__ __align__(16) __nv_bfloat16 g_hB[(size_t)MAXN * 128];
__device__ __align__(16) float g_pooled[64];

// ---------------- zero scratch ----------------------------------------------
__global__ void zero_scratch_kernel(int n) {
    int i = blockIdx.x * blockDim.x + threadIdx.x;
    int stride = gridDim.x * blockDim.x;
    for (int k = i; k < n; k += stride) {
        g_edeg[k] = 0;
        g_cur[k]  = 0;
    }
    if (i < 64) g_pooled[i] = 0.0f;
}

// ---------------- degree histogram over dst ---------------------------------
__global__ void degree_kernel(const int* __restrict__ dst, int e) {
    int i = blockIdx.x * blockDim.x + threadIdx.x;
    int stride = gridDim.x * blockDim.x;
    for (int k = i; k < e; k += stride)
        atomicAdd(&g_edeg[dst[k]], 1);
}

// ---------------- scan phase A ----------------------------------------------
__global__ void scanA_kernel(int n) {
    __shared__ int ssum[8];
    int base = blockIdx.x * SCAN_CHUNK + threadIdx.x * 4;
    int s = 0;
#pragma unroll
    for (int j = 0; j < 4; j++) {
        int idx = base + j;
        if (idx < n) {
            int d = g_edeg[idx];
            s += d;
            g_dis[idx] = rsqrtf((float)(d + 1));
        }
    }
#pragma unroll
    for (int o = 16; o > 0; o >>= 1) s += __shfl_down_sync(0xffffffffu, s, o);
    if ((threadIdx.x & 31) == 0) ssum[threadIdx.x >> 5] = s;
    __syncthreads();
    if (threadIdx.x == 0) {
        int t = 0;
#pragma unroll
        for (int w = 0; w < 8; w++) t += ssum[w];
        g_bsum[blockIdx.x] = t;
    }
}

// ---------------- scan phase B ----------------------------------------------
__global__ void scanB_kernel(int nb, int n) {
    __shared__ int sh[128];
    int t = threadIdx.x;
    int v = (t < nb) ? g_bsum[t] : 0;
    sh[t] = v;
    __syncthreads();
#pragma unroll
    for (int o = 1; o < 128; o <<= 1) {
        int u = (t >= o) ? sh[t - o] : 0;
        __syncthreads();
        sh[t] += u;
        __syncthreads();
    }
    if (t < nb) g_boff[t] = sh[t] - v;
    if (t == nb - 1) g_off[n] = sh[t];
}

// ---------------- scan phase C ----------------------------------------------
__global__ void scanC_kernel(int n) {
    __shared__ int sh[256];
    int t = threadIdx.x;
    int base = blockIdx.x * SCAN_CHUNK + t * 4;
    int d[4];
    int s = 0;
#pragma unroll
    for (int j = 0; j < 4; j++) {
        int idx = base + j;
        d[j] = (idx < n) ? g_edeg[idx] : 0;
        s += d[j];
    }
    sh[t] = s;
    __syncthreads();
#pragma unroll
    for (int o = 1; o < 256; o <<= 1) {
        int u = (t >= o) ? sh[t - o] : 0;
        __syncthreads();
        sh[t] += u;
        __syncthreads();
    }
    int run = g_boff[blockIdx.x] + sh[t] - s;
#pragma unroll
    for (int j = 0; j < 4; j++) {
        int idx = base + j;
        if (idx < n) g_off[idx] = run;
        run += d[j];
    }
}

// ---------------- CSR fill --------------------------------------------------
__global__ void fill_kernel(const int* __restrict__ src,
                            const int* __restrict__ dst, int e) {
    int i = blockIdx.x * blockDim.x + threadIdx.x;
    int stride = gridDim.x * blockDim.x;
    for (int k = i; k < e; k += stride) {
        int d = dst[k];
        int p = atomicAdd(&g_cur[d], 1);
        g_col[g_off[d] + p] = src[k];
    }
}

// ---------------- x -> bf16 -------------------------------------------------
__global__ void cvt_kernel(const float* __restrict__ x, __nv_bfloat16* __restrict__ o,
                           int total) {
    int i = blockIdx.x * blockDim.x + threadIdx.x;
    int stride = gridDim.x * blockDim.x;
    for (int k = i; k < total; k += stride)
        o[k] = __float2bfloat16_rn(x[k]);
}

// ---------------- tensor-core GEMM ------------------------------------------
// C[n,HOUT](bf16) = A[n,K](bf16) @ W[K,HOUT](f32->bf16), fp32 accumulate,
// optional fused bias+relu. Block = 256 thr (8 warps), tile 128 x HOUT,
// K chunked by 64.  mma.sync.m16n8k16 bf16.
__device__ __forceinline__ unsigned smem_u32(const void* p) {
    return (unsigned)__cvta_generic_to_shared(p);
}
__device__ __forceinline__ void ldsm_x4(unsigned& r0, unsigned& r1, unsigned& r2,
                                        unsigned& r3, unsigned addr) {
    asm volatile("ldmatrix.sync.aligned.m8n8.x4.shared.b16 {%0,%1,%2,%3}, [%4];\n"
                 : "=r"(r0), "=r"(r1), "=r"(r2), "=r"(r3) : "r"(addr));
}
__device__ __forceinline__ void ldsm_x4_t(unsigned& r0, unsigned& r1, unsigned& r2,
                                          unsigned& r3, unsigned addr) {
    asm volatile("ldmatrix.sync.aligned.m8n8.x4.trans.shared.b16 {%0,%1,%2,%3}, [%4];\n"
                 : "=r"(r0), "=r"(r1), "=r"(r2), "=r"(r3) : "r"(addr));
}
__device__ __forceinline__ void mma_bf16(float* d, const unsigned* a, const unsigned* b) {
    asm volatile(
        "mma.sync.aligned.m16n8k16.row.col.f32.bf16.bf16.f32 "
        "{%0,%1,%2,%3}, {%4,%5,%6,%7}, {%8,%9}, {%0,%1,%2,%3};\n"
        : "+f"(d[0]), "+f"(d[1]), "+f"(d[2]), "+f"(d[3])
        : "r"(a[0]), "r"(a[1]), "r"(a[2]), "r"(a[3]), "r"(b[0]), "r"(b[1]));
}

template <int K, int HOUT, bool BIASRELU>
__global__ void __launch_bounds__(256, 2)
gemm_tc_kernel(const __nv_bfloat16* __restrict__ A,
               const float* __restrict__ W,
               const float* __restrict__ bias,
               __nv_bfloat16* __restrict__ C, int n) {
    constexpr int KC = 64;                  // k-chunk
    constexpr int SA_S = KC + 8;            // sA stride (bf16)
    constexpr int SW_S = HOUT + 8;          // sW stride (bf16)
    constexpr int NT = HOUT / 8;            // n-tiles per warp
    __shared__ __nv_bfloat16 sA[128 * SA_S];
    __shared__ __nv_bfloat16 sW[KC * SW_S];

    int tid = threadIdx.x;
    int wid = tid >> 5;
    int lane = tid & 31;
    int rowBase = blockIdx.x * 128;
    int m0 = wid * 16;

    float acc[NT][4];
#pragma unroll
    for (int t = 0; t < NT; t++)
#pragma unroll
        for (int j = 0; j < 4; j++) acc[t][j] = 0.0f;

    for (int kc = 0; kc < K; kc += KC) {
        // load A tile: 128 rows x KC bf16 (uint4 = 8 bf16 per seg)
        constexpr int SEGS = KC / 8;
        for (int i = tid; i < 128 * SEGS; i += 256) {
            int r = i / SEGS, sg = i % SEGS;
            int row = rowBase + r;
            uint4 v = make_uint4(0, 0, 0, 0);
            if (row < n)
                v = *reinterpret_cast<const uint4*>(A + (size_t)row * K + kc + sg * 8);
            *reinterpret_cast<uint4*>(&sA[r * SA_S + sg * 8]) = v;
        }
        // load + convert W chunk: KC x HOUT
        constexpr int WC4 = HOUT / 4;
        for (int i = tid; i < KC * WC4; i += 256) {
            int k = i / WC4, c4 = i % WC4;
            float4 w = *reinterpret_cast<const float4*>(W + (size_t)(kc + k) * HOUT + c4 * 4);
            __nv_bfloat162 p0 = __floats2bfloat162_rn(w.x, w.y);
            __nv_bfloat162 p1 = __floats2bfloat162_rn(w.z, w.w);
            uint2 pk;
            pk.x = *reinterpret_cast<unsigned*>(&p0);
            pk.y = *reinterpret_cast<unsigned*>(&p1);
            *reinterpret_cast<uint2*>(&sW[k * SW_S + c4 * 4]) = pk;
        }
        __syncthreads();

#pragma unroll
        for (int ks = 0; ks < KC / 16; ks++) {
            int k0 = ks * 16;
            unsigned a[4];
            {
                int r = m0 + (lane & 15);
                int c = k0 + (lane >> 4) * 8;
                ldsm_x4(a[0], a[1], a[2], a[3], smem_u32(&sA[r * SA_S + c]));
            }
#pragma unroll
            for (int nt2 = 0; nt2 < NT / 2; nt2++) {
                int n0 = nt2 * 16;
                unsigned b[4];
                int rk = k0 + (lane & 15);
                int cn = n0 + (lane >> 4) * 8;
                ldsm_x4_t(b[0], b[1], b[2], b[3], smem_u32(&sW[rk * SW_S + cn]));
                mma_bf16(acc[2 * nt2], a, b);
                mma_bf16(acc[2 * nt2 + 1], a, b + 2);
            }
        }
        __syncthreads();
    }

    // epilogue: thread holds (r, c2),(r, c2+1) and (r+8, ...) per n-tile
    int r = lane >> 2;
    int c2 = (lane & 3) * 2;
#pragma unroll
    for (int t = 0; t < NT; t++) {
        int col = t * 8 + c2;
        float v0 = acc[t][0], v1 = acc[t][1], v2 = acc[t][2], v3 = acc[t][3];
        if (BIASRELU) {
            float b0 = bias[col], b1 = bias[col + 1];
            v0 = fmaxf(v0 + b0, 0.f); v1 = fmaxf(v1 + b1, 0.f);
            v2 = fmaxf(v2 + b0, 0.f); v3 = fmaxf(v3 + b1, 0.f);
        }
        int row0 = rowBase + m0 + r;
        int row1 = row0 + 8;
        if (row0 < n) {
            __nv_bfloat162 p = __floats2bfloat162_rn(v0, v1);
            *reinterpret_cast<unsigned*>(C + (size_t)row0 * HOUT + col) =
                *reinterpret_cast<unsigned*>(&p);
        }
        if (row1 < n) {
            __nv_bfloat162 p = __floats2bfloat162_rn(v2, v3);
            *reinterpret_cast<unsigned*>(C + (size_t)row1 * HOUT + col) =
                *reinterpret_cast<unsigned*>(&p);
        }
    }
}

// ---------------- aggregation (gather, atomic-free, bf16 tables) ------------
template <int W, bool BIASRELU>
__global__ void agg_kernel(const __nv_bfloat16* __restrict__ h,
                           const float* __restrict__ bias,
                           __nv_bfloat16* __restrict__ out, int n) {
    int w = (blockIdx.x * blockDim.x + threadIdx.x) >> 5;
    int lane = threadIdx.x & 31;
    if (w >= n) return;

    int beg = g_off[w], end = g_off[w + 1];
    float dd = g_dis[w];
    float d2 = dd * dd;

    if constexpr (W == 128) {
        float4 acc = make_float4(0.f, 0.f, 0.f, 0.f);
        for (int i = beg; i < end; i++) {
            int s = g_col[i];
            float wt = g_dis[s];
            uint2 u = reinterpret_cast<const uint2*>(h + (size_t)s * 128)[lane];
            __nv_bfloat162 p0 = *reinterpret_cast<__nv_bfloat162*>(&u.x);
            __nv_bfloat162 p1 = *reinterpret_cast<__nv_bfloat162*>(&u.y);
            acc.x = fmaf(wt, __bfloat162float(p0.x), acc.x);
            acc.y = fmaf(wt, __bfloat162float(p0.y), acc.y);
            acc.z = fmaf(wt, __bfloat162float(p1.x), acc.z);
            acc.w = fmaf(wt, __bfloat162float(p1.y), acc.w);
        }
        uint2 us = reinterpret_cast<const uint2*>(h + (size_t)w * 128)[lane];
        __nv_bfloat162 s0 = *reinterpret_cast<__nv_bfloat162*>(&us.x);
        __nv_bfloat162 s1 = *reinterpret_cast<__nv_bfloat162*>(&us.y);
        float4 o;
        o.x = fmaf(dd, acc.x, d2 * __bfloat162float(s0.x));
        o.y = fmaf(dd, acc.y, d2 * __bfloat162float(s0.y));
        o.z = fmaf(dd, acc.z, d2 * __bfloat162float(s1.x));
        o.w = fmaf(dd, acc.w, d2 * __bfloat162float(s1.y));
        if (BIASRELU) {
            float4 bb = reinterpret_cast<const float4*>(bias)[lane];
            o.x = fmaxf(o.x + bb.x, 0.f);
            o.y = fmaxf(o.y + bb.y, 0.f);
            o.z = fmaxf(o.z + bb.z, 0.f);
            o.w = fmaxf(o.w + bb.w, 0.f);
        }
        uint2 r;
        __nv_bfloat162 r0 = __floats2bfloat162_rn(o.x, o.y);
        __nv_bfloat162 r1 = __floats2bfloat162_rn(o.z, o.w);
        r.x = *reinterpret_cast<unsigned*>(&r0);
        r.y = *reinterpret_cast<unsigned*>(&r1);
        reinterpret_cast<uint2*>(out + (size_t)w * 128)[lane] = r;
    } else {
        float2 acc = make_float2(0.f, 0.f);
        for (int i = beg; i < end; i++) {
            int s = g_col[i];
            float wt = g_dis[s];
            unsigned u = reinterpret_cast<const unsigned*>(h + (size_t)s * 64)[lane];
            __nv_bfloat162 p = *reinterpret_cast<__nv_bfloat162*>(&u);
            acc.x = fmaf(wt, __bfloat162float(p.x), acc.x);
            acc.y = fmaf(wt, __bfloat162float(p.y), acc.y);
        }
        unsigned us = reinterpret_cast<const unsigned*>(h + (size_t)w * 64)[lane];
        __nv_bfloat162 sp = *reinterpret_cast<__nv_bfloat162*>(&us);
        float2 o;
        o.x = fmaf(dd, acc.x, d2 * __bfloat162float(sp.x));
        o.y = fmaf(dd, acc.y, d2 * __bfloat162float(sp.y));
        if (BIASRELU) {
            float2 bb = reinterpret_cast<const float2*>(bias)[lane];
            o.x = fmaxf(o.x + bb.x, 0.f);
            o.y = fmaxf(o.y + bb.y, 0.f);
        }
        __nv_bfloat162 r0 = __floats2bfloat162_rn(o.x, o.y);
        reinterpret_cast<unsigned*>(out + (size_t)w * 64)[lane] =
            *reinterpret_cast<unsigned*>(&r0);
    }
}

// ---------------- mean pool -------------------------------------------------
__global__ void pool_kernel(const __nv_bfloat16* __restrict__ h, int n) {
    int f = threadIdx.x & 63;
    int rg = threadIdx.x >> 6;
    float acc = 0.f;
    for (int r = blockIdx.x * 4 + rg; r < n; r += gridDim.x * 4)
        acc += __bfloat162float(h[(size_t)r * 64 + f]);
    __shared__ float sp[256];
    sp[threadIdx.x] = acc;
    __syncthreads();
    if (threadIdx.x < 64) {
        float v = sp[threadIdx.x] + sp[threadIdx.x + 64] +
                  sp[threadIdx.x + 128] + sp[threadIdx.x + 192];
        atomicAdd(&g_pooled[f], v);
    }
}

// ---------------- classifier + softmax --------------------------------------
__global__ void cls_kernel(const float* __restrict__ Wc1, const float* __restrict__ bc1,
                           const float* __restrict__ Wc2, const float* __restrict__ bc2,
                           float* __restrict__ out, float invN) {
    __shared__ float z[32];
    int t = threadIdx.x;
    if (t < 32) {
        float a = bc1[t];
        for (int i = 0; i < 64; i++)
            a = fmaf(g_pooled[i] * invN, Wc1[i * 32 + t], a);
        z[t] = fmaxf(a, 0.f);
    }
    __syncthreads();
    if (t == 0) {
        float l0 = bc2[0], l1 = bc2[1];
        for (int j = 0; j < 32; j++) {
            l0 = fmaf(z[j], Wc2[j * 2 + 0], l0);
            l1 = fmaf(z[j], Wc2[j * 2 + 1], l1);
        }
        float m = fmaxf(l0, l1);
        float e0 = expf(l0 - m), e1 = expf(l1 - m);
        float s = e0 + e1;
        out[0] = e0 / s;
        out[1] = e1 / s;
    }
}

// ---------------- launch -----------------------------------------------------
extern "C" void kernel_launch(void* const* d_in, const int* in_sizes, int n_in,
                              void* d_out, int out_size) {
    const float* x   = (const float*)d_in[0];
    const int*   ei  = (const int*)d_in[1];
    const float* W1  = (const float*)d_in[2];
    const float* b1  = (const float*)d_in[3];
    const float* W2  = (const float*)d_in[4];
    const float* b2  = (const float*)d_in[5];
    const float* W3  = (const float*)d_in[6];
    const float* b3  = (const float*)d_in[7];
    const float* Wc1 = (const float*)d_in[8];
    const float* bc1 = (const float*)d_in[9];
    const float* Wc2 = (const float*)d_in[10];
    const float* bc2 = (const float*)d_in[11];
    float* out = (float*)d_out;

    int n = in_sizes[0] / 64;
    int e = in_sizes[1] / 2;
    const int* src = ei;
    const int* dst = ei + e;
    int nb = (n + SCAN_CHUNK - 1) / SCAN_CHUNK;

    __nv_bfloat16* A;  cudaGetSymbolAddress((void**)&A, g_hA);
    __nv_bfloat16* B;  cudaGetSymbolAddress((void**)&B, g_hB);

    // graph prep
    zero_scratch_kernel<<<512, 256>>>(n);
    degree_kernel<<<2048, 256>>>(dst, e);
    scanA_kernel<<<nb, 256>>>(n);
    scanB_kernel<<<1, 128>>>(nb, n);
    scanC_kernel<<<nb, 256>>>(n);
    fill_kernel<<<2048, 256>>>(src, dst, e);

    // x -> bf16
    cvt_kernel<<<1024, 256>>>(x, A, n * 64);

    int gg = (n + 127) / 128;
    // layer 1 (reordered): aggregate x (width 64) first, then tc-GEMM + bias + relu
    agg_kernel<64, false><<<(n + 7) / 8, 256>>>(A, nullptr, B, n);
    gemm_tc_kernel<64, 128, true><<<gg, 256>>>(B, W1, b1, A, n);
    // layer 2
    gemm_tc_kernel<128, 128, false><<<gg, 256>>>(A, W2, nullptr, B, n);
    agg_kernel<128, true><<<(n + 7) / 8, 256>>>(B, b2, A, n);
    // layer 3
    gemm_tc_kernel<128, 64, false><<<gg, 256>>>(A, W3, nullptr, B, n);
    agg_kernel<64, true><<<(n + 7) / 8, 256>>>(B, b3, A, n);

    // pool + classifier
    pool_kernel<<<256, 256>>>(A, n);
    cls_kernel<<<1, 64>>>(Wc1, bc1, Wc2, bc2, out, 1.0f / (float)n);
}

// round 8
// speedup vs baseline: 3.8213x; 1.5338x over previous
#include <cuda_runtime.h>
#include <cuda_bf16.h>
#include <math.h>

#define MAXN 100000
#define MAXE 1600000
#define SCAN_CHUNK 1024

// ---------------- scratch ---------------------------------------------------
__device__ __align__(16) int   g_edeg[MAXN];
__device__ __align__(16) float g_dis[MAXN];
__device__ __align__(16) int   g_off[MAXN + 1];   // after fill: inclusive ends
__device__ __align__(16) int   g_col[MAXE];
__device__ __align__(16) int   g_bsum[128];
__device__ __align__(16) __nv_bfloat16 g_hA[(size_t)MAXN * 128];
__device__ __align__(16) __nv_bfloat16 g_hB[(size_t)MAXN * 128];
__device__ __align__(16) float g_pooled[64];

// ---------------- zero scratch ----------------------------------------------
__global__ void zero_kernel(int n) {
    int i = blockIdx.x * blockDim.x + threadIdx.x;
    int stride = gridDim.x * blockDim.x;
    for (int k = i; k < n; k += stride) g_edeg[k] = 0;
    if (i < 64) g_pooled[i] = 0.0f;
}

// ---------------- degree histogram over dst ---------------------------------
__global__ void degree_kernel(const int* __restrict__ dst, int e) {
    int i = blockIdx.x * blockDim.x + threadIdx.x;
    int stride = gridDim.x * blockDim.x;
    for (int k = i; k < e; k += stride)
        atomicAdd(&g_edeg[dst[k]], 1);
}

// ---------------- scan phase A: per-block sums + dis ------------------------
__global__ void scanA_kernel(int n) {
    __shared__ int ssum[8];
    int base = blockIdx.x * SCAN_CHUNK + threadIdx.x * 4;
    int s = 0;
#pragma unroll
    for (int j = 0; j < 4; j++) {
        int idx = base + j;
        if (idx < n) {
            int d = g_edeg[idx];
            s += d;
            g_dis[idx] = rsqrtf((float)(d + 1));
        }
    }
#pragma unroll
    for (int o = 16; o > 0; o >>= 1) s += __shfl_down_sync(0xffffffffu, s, o);
    if ((threadIdx.x & 31) == 0) ssum[threadIdx.x >> 5] = s;
    __syncthreads();
    if (threadIdx.x == 0) {
        int t = 0;
#pragma unroll
        for (int w = 0; w < 8; w++) t += ssum[w];
        g_bsum[blockIdx.x] = t;
    }
}

// ---------------- x -> bf16, prescaled by dis[row] --------------------------
__global__ void cvt_kernel(const float* __restrict__ x, __nv_bfloat16* __restrict__ o,
                           int total) {
    int i = blockIdx.x * blockDim.x + threadIdx.x;
    int stride = gridDim.x * blockDim.x;
    for (int k = i; k < total; k += stride)
        o[k] = __float2bfloat16_rn(x[k] * g_dis[k >> 6]);
}

// ---------------- scan phase C (with inline block-sum scan) -----------------
__global__ void scanC_kernel(int nb, int n) {
    __shared__ int sb[128];
    __shared__ int sh[256];
    int t = threadIdx.x;
    if (t < 128) sb[t] = (t < nb) ? g_bsum[t] : 0;
    __syncthreads();
#pragma unroll
    for (int o = 1; o < 128; o <<= 1) {
        int u = (t >= o && t < 128) ? sb[t - o] : 0;
        __syncthreads();
        if (t < 128) sb[t] += u;
        __syncthreads();
    }
    int boff = (blockIdx.x == 0) ? 0 : sb[blockIdx.x - 1];
    if (blockIdx.x == 0 && t == 0) g_off[n] = sb[127];

    int base = blockIdx.x * SCAN_CHUNK + t * 4;
    int d[4];
    int s = 0;
#pragma unroll
    for (int j = 0; j < 4; j++) {
        int idx = base + j;
        d[j] = (idx < n) ? g_edeg[idx] : 0;
        s += d[j];
    }
    sh[t] = s;
    __syncthreads();
#pragma unroll
    for (int o = 1; o < 256; o <<= 1) {
        int u = (t >= o) ? sh[t - o] : 0;
        __syncthreads();
        sh[t] += u;
        __syncthreads();
    }
    int run = boff + sh[t] - s;
#pragma unroll
    for (int j = 0; j < 4; j++) {
        int idx = base + j;
        if (idx < n) g_off[idx] = run;
        run += d[j];
    }
}

// ---------------- CSR fill (in-place cursor on g_off) -----------------------
__global__ void fill_kernel(const int* __restrict__ src,
                            const int* __restrict__ dst, int e) {
    int i = blockIdx.x * blockDim.x + threadIdx.x;
    int stride = gridDim.x * blockDim.x;
    for (int k = i; k < e; k += stride) {
        int p = atomicAdd(&g_off[dst[k]], 1);
        g_col[p] = src[k];
    }
}

// ---------------- tensor-core GEMM ------------------------------------------
__device__ __forceinline__ unsigned smem_u32(const void* p) {
    return (unsigned)__cvta_generic_to_shared(p);
}
__device__ __forceinline__ void ldsm_x4(unsigned& r0, unsigned& r1, unsigned& r2,
                                        unsigned& r3, unsigned addr) {
    asm volatile("ldmatrix.sync.aligned.m8n8.x4.shared.b16 {%0,%1,%2,%3}, [%4];\n"
                 : "=r"(r0), "=r"(r1), "=r"(r2), "=r"(r3) : "r"(addr));
}
__device__ __forceinline__ void ldsm_x4_t(unsigned& r0, unsigned& r1, unsigned& r2,
                                          unsigned& r3, unsigned addr) {
    asm volatile("ldmatrix.sync.aligned.m8n8.x4.trans.shared.b16 {%0,%1,%2,%3}, [%4];\n"
                 : "=r"(r0), "=r"(r1), "=r"(r2), "=r"(r3) : "r"(addr));
}
__device__ __forceinline__ void mma_bf16(float* d, const unsigned* a, const unsigned* b) {
    asm volatile(
        "mma.sync.aligned.m16n8k16.row.col.f32.bf16.bf16.f32 "
        "{%0,%1,%2,%3}, {%4,%5,%6,%7}, {%8,%9}, {%0,%1,%2,%3};\n"
        : "+f"(d[0]), "+f"(d[1]), "+f"(d[2]), "+f"(d[3])
        : "r"(a[0]), "r"(a[1]), "r"(a[2]), "r"(a[3]), "r"(b[0]), "r"(b[1]));
}

// C[n,HOUT](bf16) = A[n,K](bf16) @ W(f32->bf16); fp32 accum.
// BIASRELU: v = relu(v + bias).  DISSCALE: v *= dis[row] AFTER bias/relu.
// (DISSCALE is used ONLY when the GEMM input was an unscaled table; when the
//  input table is already dis-prescaled, the GEMM output is inherently scaled.)
template <int K, int HOUT, bool BIASRELU, bool DISSCALE>
__global__ void __launch_bounds__(256, 2)
gemm_tc_kernel(const __nv_bfloat16* __restrict__ A,
               const float* __restrict__ W,
               const float* __restrict__ bias,
               __nv_bfloat16* __restrict__ C, int n) {
    constexpr int KC = 64;
    constexpr int SA_S = KC + 8;
    constexpr int SW_S = HOUT + 8;
    constexpr int NT = HOUT / 8;
    __shared__ __nv_bfloat16 sA[128 * SA_S];
    __shared__ __nv_bfloat16 sW[KC * SW_S];

    int tid = threadIdx.x;
    int wid = tid >> 5;
    int lane = tid & 31;
    int rowBase = blockIdx.x * 128;
    int m0 = wid * 16;

    float acc[NT][4];
#pragma unroll
    for (int t = 0; t < NT; t++)
#pragma unroll
        for (int j = 0; j < 4; j++) acc[t][j] = 0.0f;

    for (int kc = 0; kc < K; kc += KC) {
        constexpr int SEGS = KC / 8;
        for (int i = tid; i < 128 * SEGS; i += 256) {
            int r = i / SEGS, sg = i % SEGS;
            int row = rowBase + r;
            uint4 v = make_uint4(0, 0, 0, 0);
            if (row < n)
                v = *reinterpret_cast<const uint4*>(A + (size_t)row * K + kc + sg * 8);
            *reinterpret_cast<uint4*>(&sA[r * SA_S + sg * 8]) = v;
        }
        constexpr int WC4 = HOUT / 4;
        for (int i = tid; i < KC * WC4; i += 256) {
            int k = i / WC4, c4 = i % WC4;
            float4 w = *reinterpret_cast<const float4*>(W + (size_t)(kc + k) * HOUT + c4 * 4);
            __nv_bfloat162 p0 = __floats2bfloat162_rn(w.x, w.y);
            __nv_bfloat162 p1 = __floats2bfloat162_rn(w.z, w.w);
            uint2 pk;
            pk.x = *reinterpret_cast<unsigned*>(&p0);
            pk.y = *reinterpret_cast<unsigned*>(&p1);
            *reinterpret_cast<uint2*>(&sW[k * SW_S + c4 * 4]) = pk;
        }
        __syncthreads();

#pragma unroll
        for (int ks = 0; ks < KC / 16; ks++) {
            int k0 = ks * 16;
            unsigned a[4];
            {
                int r = m0 + (lane & 15);
                int c = k0 + (lane >> 4) * 8;
                ldsm_x4(a[0], a[1], a[2], a[3], smem_u32(&sA[r * SA_S + c]));
            }
#pragma unroll
            for (int nt2 = 0; nt2 < NT / 2; nt2++) {
                int n0 = nt2 * 16;
                unsigned b[4];
                int rk = k0 + (lane & 15);
                int cn = n0 + (lane >> 4) * 8;
                ldsm_x4_t(b[0], b[1], b[2], b[3], smem_u32(&sW[rk * SW_S + cn]));
                mma_bf16(acc[2 * nt2], a, b);
                mma_bf16(acc[2 * nt2 + 1], a, b + 2);
            }
        }
        __syncthreads();
    }

    int r = lane >> 2;
    int c2 = (lane & 3) * 2;
    int row0 = rowBase + m0 + r;
    int row1 = row0 + 8;
    float ds0 = 1.f, ds1 = 1.f;
    if (DISSCALE) {
        if (row0 < n) ds0 = g_dis[row0];
        if (row1 < n) ds1 = g_dis[row1];
    }
#pragma unroll
    for (int t = 0; t < NT; t++) {
        int col = t * 8 + c2;
        float v0 = acc[t][0], v1 = acc[t][1], v2 = acc[t][2], v3 = acc[t][3];
        if (BIASRELU) {
            float b0 = bias[col], b1 = bias[col + 1];
            v0 = fmaxf(v0 + b0, 0.f); v1 = fmaxf(v1 + b1, 0.f);
            v2 = fmaxf(v2 + b0, 0.f); v3 = fmaxf(v3 + b1, 0.f);
        }
        if (DISSCALE) { v0 *= ds0; v1 *= ds0; v2 *= ds1; v3 *= ds1; }
        if (row0 < n) {
            __nv_bfloat162 p = __floats2bfloat162_rn(v0, v1);
            *reinterpret_cast<unsigned*>(C + (size_t)row0 * HOUT + col) =
                *reinterpret_cast<unsigned*>(&p);
        }
        if (row1 < n) {
            __nv_bfloat162 p = __floats2bfloat162_rn(v2, v3);
            *reinterpret_cast<unsigned*>(C + (size_t)row1 * HOUT + col) =
                *reinterpret_cast<unsigned*>(&p);
        }
    }
}

// ---------------- aggregation: pure row-sum over prescaled message tables ---
// messages m[s] come in already dis[s]-scaled. Computes
//   v = dd * (sum_{s in N(d)} m[s] + m[d])        (self term -> dd*m[d] = dis^2*(..))
//   if BIASRELU: v = relu(v + b)
//   if OUTSCALE: v *= dd        (pre-scales the table for the NEXT layer's GEMM)
template <int W, bool BIASRELU, bool OUTSCALE>
__global__ void agg_kernel(const __nv_bfloat16* __restrict__ h,
                           const float* __restrict__ bias,
                           __nv_bfloat16* __restrict__ out, int n) {
    int w = (blockIdx.x * blockDim.x + threadIdx.x) >> 5;
    int lane = threadIdx.x & 31;
    if (w >= n) return;

    int beg = (w == 0) ? 0 : g_off[w - 1];
    int end = g_off[w];
    float dd = g_dis[w];

    if constexpr (W == 128) {
        float4 a0 = make_float4(0.f, 0.f, 0.f, 0.f);
        float4 a1 = make_float4(0.f, 0.f, 0.f, 0.f);
        int i = beg;
        for (; i + 2 <= end; i += 2) {
            int s0 = g_col[i], s1 = g_col[i + 1];
            uint2 u0 = reinterpret_cast<const uint2*>(h + (size_t)s0 * 128)[lane];
            uint2 u1 = reinterpret_cast<const uint2*>(h + (size_t)s1 * 128)[lane];
            float2 p00 = __bfloat1622float2(*reinterpret_cast<__nv_bfloat162*>(&u0.x));
            float2 p01 = __bfloat1622float2(*reinterpret_cast<__nv_bfloat162*>(&u0.y));
            float2 p10 = __bfloat1622float2(*reinterpret_cast<__nv_bfloat162*>(&u1.x));
            float2 p11 = __bfloat1622float2(*reinterpret_cast<__nv_bfloat162*>(&u1.y));
            a0.x += p00.x; a0.y += p00.y; a0.z += p01.x; a0.w += p01.y;
            a1.x += p10.x; a1.y += p10.y; a1.z += p11.x; a1.w += p11.y;
        }
        if (i < end) {
            int s0 = g_col[i];
            uint2 u0 = reinterpret_cast<const uint2*>(h + (size_t)s0 * 128)[lane];
            float2 p00 = __bfloat1622float2(*reinterpret_cast<__nv_bfloat162*>(&u0.x));
            float2 p01 = __bfloat1622float2(*reinterpret_cast<__nv_bfloat162*>(&u0.y));
            a0.x += p00.x; a0.y += p00.y; a0.z += p01.x; a0.w += p01.y;
        }
        {   // self row
            uint2 us = reinterpret_cast<const uint2*>(h + (size_t)w * 128)[lane];
            float2 s0 = __bfloat1622float2(*reinterpret_cast<__nv_bfloat162*>(&us.x));
            float2 s1 = __bfloat1622float2(*reinterpret_cast<__nv_bfloat162*>(&us.y));
            a0.x += s0.x; a0.y += s0.y; a0.z += s1.x; a0.w += s1.y;
        }
        float4 o;
        o.x = dd * (a0.x + a1.x);
        o.y = dd * (a0.y + a1.y);
        o.z = dd * (a0.z + a1.z);
        o.w = dd * (a0.w + a1.w);
        if (BIASRELU) {
            float4 bb = reinterpret_cast<const float4*>(bias)[lane];
            o.x = fmaxf(o.x + bb.x, 0.f);
            o.y = fmaxf(o.y + bb.y, 0.f);
            o.z = fmaxf(o.z + bb.z, 0.f);
            o.w = fmaxf(o.w + bb.w, 0.f);
        }
        if (OUTSCALE) { o.x *= dd; o.y *= dd; o.z *= dd; o.w *= dd; }
        uint2 r;
        __nv_bfloat162 r0 = __floats2bfloat162_rn(o.x, o.y);
        __nv_bfloat162 r1 = __floats2bfloat162_rn(o.z, o.w);
        r.x = *reinterpret_cast<unsigned*>(&r0);
        r.y = *reinterpret_cast<unsigned*>(&r1);
        reinterpret_cast<uint2*>(out + (size_t)w * 128)[lane] = r;
    } else {  // W == 64
        float2 a0 = make_float2(0.f, 0.f);
        float2 a1 = make_float2(0.f, 0.f);
        int i = beg;
        for (; i + 2 <= end; i += 2) {
            int s0 = g_col[i], s1 = g_col[i + 1];
            unsigned u0 = reinterpret_cast<const unsigned*>(h + (size_t)s0 * 64)[lane];
            unsigned u1 = reinterpret_cast<const unsigned*>(h + (size_t)s1 * 64)[lane];
            float2 p0 = __bfloat1622float2(*reinterpret_cast<__nv_bfloat162*>(&u0));
            float2 p1 = __bfloat1622float2(*reinterpret_cast<__nv_bfloat162*>(&u1));
            a0.x += p0.x; a0.y += p0.y;
            a1.x += p1.x; a1.y += p1.y;
        }
        if (i < end) {
            int s0 = g_col[i];
            unsigned u0 = reinterpret_cast<const unsigned*>(h + (size_t)s0 * 64)[lane];
            float2 p0 = __bfloat1622float2(*reinterpret_cast<__nv_bfloat162*>(&u0));
            a0.x += p0.x; a0.y += p0.y;
        }
        {
            unsigned us = reinterpret_cast<const unsigned*>(h + (size_t)w * 64)[lane];
            float2 sp = __bfloat1622float2(*reinterpret_cast<__nv_bfloat162*>(&us));
            a0.x += sp.x; a0.y += sp.y;
        }
        float2 o;
        o.x = dd * (a0.x + a1.x);
        o.y = dd * (a0.y + a1.y);
        if (BIASRELU) {
            float2 bb = reinterpret_cast<const float2*>(bias)[lane];
            o.x = fmaxf(o.x + bb.x, 0.f);
            o.y = fmaxf(o.y + bb.y, 0.f);
        }
        if (OUTSCALE) { o.x *= dd; o.y *= dd; }
        __nv_bfloat162 r0 = __floats2bfloat162_rn(o.x, o.y);
        reinterpret_cast<unsigned*>(out + (size_t)w * 64)[lane] =
            *reinterpret_cast<unsigned*>(&r0);
    }
}

// ---------------- layer-3 aggregation fused with mean pool ------------------
__global__ void agg_pool_kernel(const __nv_bfloat16* __restrict__ h,
                                const float* __restrict__ bias, int n) {
    __shared__ float sp[64];
    int tid = threadIdx.x;
    if (tid < 64) sp[tid] = 0.f;
    __syncthreads();

    int w = (blockIdx.x * blockDim.x + tid) >> 5;
    int lane = tid & 31;
    if (w < n) {
        int beg = (w == 0) ? 0 : g_off[w - 1];
        int end = g_off[w];
        float dd = g_dis[w];
        float2 a0 = make_float2(0.f, 0.f);
        float2 a1 = make_float2(0.f, 0.f);
        int i = beg;
        for (; i + 2 <= end; i += 2) {
            int s0 = g_col[i], s1 = g_col[i + 1];
            unsigned u0 = reinterpret_cast<const unsigned*>(h + (size_t)s0 * 64)[lane];
            unsigned u1 = reinterpret_cast<const unsigned*>(h + (size_t)s1 * 64)[lane];
            float2 p0 = __bfloat1622float2(*reinterpret_cast<__nv_bfloat162*>(&u0));
            float2 p1 = __bfloat1622float2(*reinterpret_cast<__nv_bfloat162*>(&u1));
            a0.x += p0.x; a0.y += p0.y;
            a1.x += p1.x; a1.y += p1.y;
        }
        if (i < end) {
            int s0 = g_col[i];
            unsigned u0 = reinterpret_cast<const unsigned*>(h + (size_t)s0 * 64)[lane];
            float2 p0 = __bfloat1622float2(*reinterpret_cast<__nv_bfloat162*>(&u0));
            a0.x += p0.x; a0.y += p0.y;
        }
        unsigned us = reinterpret_cast<const unsigned*>(h + (size_t)w * 64)[lane];
        float2 spv = __bfloat1622float2(*reinterpret_cast<__nv_bfloat162*>(&us));
        a0.x += spv.x; a0.y += spv.y;

        float2 bb = reinterpret_cast<const float2*>(bias)[lane];
        float o0 = fmaxf(dd * (a0.x + a1.x) + bb.x, 0.f);
        float o1 = fmaxf(dd * (a0.y + a1.y) + bb.y, 0.f);
        atomicAdd(&sp[lane * 2], o0);
        atomicAdd(&sp[lane * 2 + 1], o1);
    }
    __syncthreads();
    if (tid < 64) atomicAdd(&g_pooled[tid], sp[tid]);
}

// ---------------- classifier + softmax --------------------------------------
__global__ void cls_kernel(const float* __restrict__ Wc1, const float* __restrict__ bc1,
                           const float* __restrict__ Wc2, const float* __restrict__ bc2,
                           float* __restrict__ out, float invN) {
    __shared__ float z[32];
    int t = threadIdx.x;
    if (t < 32) {
        float a = bc1[t];
        for (int i = 0; i < 64; i++)
            a = fmaf(g_pooled[i] * invN, Wc1[i * 32 + t], a);
        z[t] = fmaxf(a, 0.f);
    }
    __syncthreads();
    if (t == 0) {
        float l0 = bc2[0], l1 = bc2[1];
        for (int j = 0; j < 32; j++) {
            l0 = fmaf(z[j], Wc2[j * 2 + 0], l0);
            l1 = fmaf(z[j], Wc2[j * 2 + 1], l1);
        }
        float m = fmaxf(l0, l1);
        float e0 = expf(l0 - m), e1 = expf(l1 - m);
        float s = e0 + e1;
        out[0] = e0 / s;
        out[1] = e1 / s;
    }
}

// ---------------- launch -----------------------------------------------------
extern "C" void kernel_launch(void* const* d_in, const int* in_sizes, int n_in,
                              void* d_out, int out_size) {
    const float* x   = (const float*)d_in[0];
    const int*   ei  = (const int*)d_in[1];
    const float* W1  = (const float*)d_in[2];
    const float* b1  = (const float*)d_in[3];
    const float* W2  = (const float*)d_in[4];
    const float* b2  = (const float*)d_in[5];
    const float* W3  = (const float*)d_in[6];
    const float* b3  = (const float*)d_in[7];
    const float* Wc1 = (const float*)d_in[8];
    const float* bc1 = (const float*)d_in[9];
    const float* Wc2 = (const float*)d_in[10];
    const float* bc2 = (const float*)d_in[11];
    float* out = (float*)d_out;

    int n = in_sizes[0] / 64;
    int e = in_sizes[1] / 2;
    const int* src = ei;
    const int* dst = ei + e;
    int nb = (n + SCAN_CHUNK - 1) / SCAN_CHUNK;

    __nv_bfloat16* A;  cudaGetSymbolAddress((void**)&A, g_hA);
    __nv_bfloat16* B;  cudaGetSymbolAddress((void**)&B, g_hB);

    // graph prep
    zero_kernel<<<512, 256>>>(n);
    degree_kernel<<<2048, 256>>>(dst, e);
    scanA_kernel<<<nb, 256>>>(n);                 // deg sums + dis
    cvt_kernel<<<1024, 256>>>(x, A, n * 64);      // x -> dis-prescaled bf16 (T0)
    scanC_kernel<<<nb, 256>>>(nb, n);             // offsets
    fill_kernel<<<2048, 256>>>(src, dst, e);      // CSR (in-place cursors)

    int gg = (n + 127) / 128;
    // layer 1: agg(T0) -> unscaled a ; gemm1: relu(a@W1+b1)*dis -> T1 (prescaled)
    agg_kernel<64, false, false><<<(n + 7) / 8, 256>>>(A, nullptr, B, n);
    gemm_tc_kernel<64, 128, true, true><<<gg, 256>>>(B, W1, b1, A, n);
    // layer 2: gemm2(T1@W2) = messages (already dis-scaled; NO disscale);
    //          agg2: relu(dd*sum+b2) * dd -> T2 (prescaled)
    gemm_tc_kernel<128, 128, false, false><<<gg, 256>>>(A, W2, nullptr, B, n);
    agg_kernel<128, true, true><<<(n + 7) / 8, 256>>>(B, b2, A, n);
    // layer 3: gemm3(T2@W3) = messages (NO disscale); agg+pool: relu(dd*sum+b3)
    gemm_tc_kernel<128, 64, false, false><<<gg, 256>>>(A, W3, nullptr, B, n);
    agg_pool_kernel<<<(n + 7) / 8, 256>>>(B, b3, n);

    cls_kernel<<<1, 64>>>(Wc1, bc1, Wc2, bc2, out, 1.0f / (float)n);
}